// round 3
// baseline (speedup 1.0000x reference)
#include <cuda_runtime.h>
#include <cuda_bf16.h>
#include <stdint.h>

// ============================================================================
// Problem dims
// ============================================================================
#define M_DIM 8192       // 4 * 2048 tokens
#define K_DIM 4096       // in_features
#define N_DIM 16384      // out_features

// GEMM tiling
#define BM 128
#define BN 256
#define BK 64            // int8 K elements per chunk (64 bytes per row)
#define NKC (K_DIM / BK) // 64 chunks
#define STAGES 3
#define STAGE_BYTES ((BM + BN) * BK)     // 24576
#define GEMM_SMEM (STAGES * STAGE_BYTES) // 73728

// ============================================================================
// Scratch (static device memory — no allocations allowed)
// ============================================================================
__device__ __align__(128) int8_t g_xq[(size_t)M_DIM * K_DIM];  // 32 MB int4-valued
__device__ __align__(128) int8_t g_wt[(size_t)N_DIM * K_DIM];  // 64 MB ternary
__device__ float  g_sx[M_DIM];
__device__ double g_partial[2048];
__device__ float  g_wscale;

// ============================================================================
// PTX helpers (base sm_103 ISA only — no tcgen05)
// ============================================================================
__device__ __forceinline__ uint32_t smem_u32(const void* p) {
    uint32_t a;
    asm("{ .reg .u64 t; cvta.to.shared.u64 t, %1; cvt.u32.u64 %0, t; }" : "=r"(a) : "l"(p));
    return a;
}
__device__ __forceinline__ void cp16(uint32_t dst, const void* src) {
    asm volatile("cp.async.cg.shared.global [%0], [%1], 16;\n" :: "r"(dst), "l"(src) : "memory");
}
__device__ __forceinline__ void cp_commit() { asm volatile("cp.async.commit_group;" ::: "memory"); }
__device__ __forceinline__ void cp_wait1()  { asm volatile("cp.async.wait_group 1;" ::: "memory"); }
__device__ __forceinline__ void cp_wait0()  { asm volatile("cp.async.wait_group 0;" ::: "memory"); }

__device__ __forceinline__ void ldm_x4(uint32_t* r, uint32_t addr) {
    asm volatile("ldmatrix.sync.aligned.m8n8.x4.shared.b16 {%0,%1,%2,%3}, [%4];"
                 : "=r"(r[0]), "=r"(r[1]), "=r"(r[2]), "=r"(r[3]) : "r"(addr));
}
__device__ __forceinline__ void imma(int* c, const uint32_t* a, const uint32_t* b) {
    asm volatile("mma.sync.aligned.m16n8k32.row.col.s32.s8.s8.s32 "
                 "{%0,%1,%2,%3}, {%4,%5,%6,%7}, {%8,%9}, {%0,%1,%2,%3};"
                 : "+r"(c[0]), "+r"(c[1]), "+r"(c[2]), "+r"(c[3])
                 : "r"(a[0]), "r"(a[1]), "r"(a[2]), "r"(a[3]), "r"(b[0]), "r"(b[1]));
}

// Swizzle: 16B granule offset kb (bits 4-5) XORed with row-pair id.
// NOTE: k-offsets must be composed by XOR (bits 4-5 are inside the swizzled
// field); adding after the swizzle carries into the row field.
__device__ __forceinline__ uint32_t swz(int row, int kb) {
    return (uint32_t)(row * 64 + (kb ^ (((row >> 1) & 3) << 4)));
}

// ============================================================================
// Kernel 1: |w| partial sums. grid 2048 x 256, each block covers 32768 floats.
// ============================================================================
__global__ void k_wabs(const float* __restrict__ w) {
    int tid = threadIdx.x;
    const float4* wp = reinterpret_cast<const float4*>(w) + (size_t)blockIdx.x * 8192;
    float ssum = 0.f;
#pragma unroll
    for (int i = 0; i < 32; i++) {
        float4 v = wp[tid + i * 256];
        ssum += fabsf(v.x) + fabsf(v.y) + fabsf(v.z) + fabsf(v.w);
    }
#pragma unroll
    for (int o = 16; o > 0; o >>= 1) ssum += __shfl_xor_sync(0xffffffffu, ssum, o);
    __shared__ double wsum[8];
    if ((tid & 31) == 0) wsum[tid >> 5] = (double)ssum;
    __syncthreads();
    if (tid == 0) {
        double t = 0.0;
#pragma unroll
        for (int i = 0; i < 8; i++) t += wsum[i];
        g_partial[blockIdx.x] = t;
    }
}

// Kernel 2: final reduce -> wscale
__global__ void k_wscale(void) {
    int tid = threadIdx.x; // 256
    double t = 0.0;
#pragma unroll
    for (int i = 0; i < 8; i++) t += g_partial[tid + i * 256];
    __shared__ double sm[256];
    sm[tid] = t;
    __syncthreads();
    if (tid == 0) {
        double a = 0.0;
        for (int i = 0; i < 256; i++) a += sm[i];
        float mean = (float)(a / 67108864.0);
        g_wscale = fmaxf(mean, 1e-5f);
    }
}

// Kernel 3: ternarize weights -> int8 via half-scale threshold (== round-half-even
// of w/scale clipped to [-1,1], up to 1-ulp boundary cases). grid 16384 x 256.
__global__ void k_wquant(const float* __restrict__ w) {
    float half = 0.5f * g_wscale;
    size_t base = (size_t)blockIdx.x * 1024 + threadIdx.x; // float4 units
    const float4* wp = reinterpret_cast<const float4*>(w);
    int* o = reinterpret_cast<int*>(g_wt);
#pragma unroll
    for (int i = 0; i < 4; i++) {
        size_t idx = base + (size_t)i * 256;
        float4 v = wp[idx];
        int a = (v.x > half) - (v.x < -half);
        int b = (v.y > half) - (v.y < -half);
        int c = (v.z > half) - (v.z < -half);
        int d = (v.w > half) - (v.w < -half);
        o[idx] = (a & 0xff) | ((b & 0xff) << 8) | ((c & 0xff) << 16) | (d << 24);
    }
}

// Kernel 4: per-token int4 quant of x -> int8 + s[token]. grid 8192 x 128.
__global__ void k_xquant(const float* __restrict__ x) {
    int token = blockIdx.x;
    int tid = threadIdx.x;
    const float4* xin = reinterpret_cast<const float4*>(x + (size_t)token * K_DIM);
    float4 v[8];
    float amax = 0.f;
#pragma unroll
    for (int i = 0; i < 8; i++) {
        v[i] = xin[tid + i * 128];
        amax = fmaxf(amax, fmaxf(fmaxf(fabsf(v[i].x), fabsf(v[i].y)),
                                 fmaxf(fabsf(v[i].z), fabsf(v[i].w))));
    }
#pragma unroll
    for (int o = 16; o > 0; o >>= 1) amax = fmaxf(amax, __shfl_xor_sync(0xffffffffu, amax, o));
    __shared__ float wmax[4];
    if ((tid & 31) == 0) wmax[tid >> 5] = amax;
    __syncthreads();
    amax = fmaxf(fmaxf(wmax[0], wmax[1]), fmaxf(wmax[2], wmax[3]));
    float s = __fdiv_rn(fmaxf(amax, 1e-5f), 7.0f);
    float inv = __fdiv_rn(1.0f, s);
    if (tid == 0) g_sx[token] = s;
    int* qo = reinterpret_cast<int*>(g_xq + (size_t)token * K_DIM);
#pragma unroll
    for (int i = 0; i < 8; i++) {
        int a = (int)fminf(fmaxf(rintf(v[i].x * inv), -8.f), 7.f);
        int b = (int)fminf(fmaxf(rintf(v[i].y * inv), -8.f), 7.f);
        int c = (int)fminf(fmaxf(rintf(v[i].z * inv), -8.f), 7.f);
        int d = (int)fminf(fmaxf(rintf(v[i].w * inv), -8.f), 7.f);
        qo[tid + i * 128] = (a & 0xff) | ((b & 0xff) << 8) | ((c & 0xff) << 16) | (d << 24);
    }
}

// ============================================================================
// Kernel 5: int8 IMMA GEMM. BM=128 x BN=256 x BK=64, 3-stage cp.async,
// 8 warps of 64x64, ldmatrix fragment loads, swizzled SMEM.
// ============================================================================
__device__ __forceinline__ void load_chunk(uint32_t stage, const int8_t* Abase,
                                           const int8_t* Bbase, int kc, int tid) {
    uint32_t a_s = stage;
    uint32_t b_s = stage + BM * BK;
    const int8_t* ag = Abase + kc * BK;
    const int8_t* bg = Bbase + kc * BK;
    // A: 128 rows x 4 granules = 512, 2 per thread
#pragma unroll
    for (int i = 0; i < 2; i++) {
        int g = tid + 256 * i;
        int r = g >> 2, c = g & 3;
        cp16(a_s + swz(r, c * 16), ag + (size_t)r * K_DIM + c * 16);
    }
    // B: 256 rows x 4 granules = 1024, 4 per thread
#pragma unroll
    for (int i = 0; i < 4; i++) {
        int g = tid + 256 * i;
        int r = g >> 2, c = g & 3;
        cp16(b_s + swz(r, c * 16), bg + (size_t)r * K_DIM + c * 16);
    }
    cp_commit();
}

__global__ void __launch_bounds__(256, 1) k_gemm(float* __restrict__ out) {
    extern __shared__ char smem[];
    uint32_t sb = smem_u32(smem);
    int tid = threadIdx.x;
    int wid = tid >> 5;
    int lane = tid & 31;

    // Grouped rasterization for L2 reuse
    const int num_pid_n = N_DIM / BN; // 64
    const int GROUP = 8;
    int pid = blockIdx.x;
    int npg = GROUP * num_pid_n;
    int group_id = pid / npg;
    int first_m = group_id * GROUP;
    int pid_m = first_m + ((pid % npg) % GROUP);
    int pid_n = (pid % npg) / GROUP;

    const int8_t* Abase = g_xq + (size_t)pid_m * BM * K_DIM;
    const int8_t* Bbase = g_wt + (size_t)pid_n * BN * K_DIM;

    int WM = (wid >> 2) * 64;  // warp m offset (0 or 64)
    int WN = (wid & 3) * 64;   // warp n offset (0,64,128,192)

    int acc[4][8][4];
#pragma unroll
    for (int i = 0; i < 4; i++)
#pragma unroll
        for (int j = 0; j < 8; j++)
#pragma unroll
            for (int q = 0; q < 4; q++) acc[i][j][q] = 0;

    // Precompute per-thread ldmatrix smem offsets (ks=0 base; ks selects bit 5
    // via XOR — the k-offset lives inside the swizzled bit-field).
    uint32_t a_off[4];
#pragma unroll
    for (int i = 0; i < 4; i++) {
        int row = WM + 16 * i + (lane & 15);
        a_off[i] = swz(row, ((lane >> 4) & 1) * 16);
    }
    uint32_t b_off[4];
#pragma unroll
    for (int p = 0; p < 4; p++) {
        int n = WN + 16 * p + (lane & 7) + ((lane >> 4) & 1) * 8;
        b_off[p] = (uint32_t)(BM * BK) + swz(n, ((lane >> 3) & 1) * 16);
    }

    // Prologue
    load_chunk(sb + 0 * STAGE_BYTES, Abase, Bbase, 0, tid);
    load_chunk(sb + 1 * STAGE_BYTES, Abase, Bbase, 1, tid);

    int slot = 0;
#pragma unroll 1
    for (int kc = 0; kc < NKC; kc++) {
        if (kc >= NKC - 2) cp_wait0(); else cp_wait1();
        __syncthreads();
        // Refill the slot freed last iteration
        if (kc + 2 < NKC) {
            int ns = slot - 1; if (ns < 0) ns += STAGES;
            load_chunk(sb + ns * STAGE_BYTES, Abase, Bbase, kc + 2, tid);
        }
        uint32_t stage = sb + slot * STAGE_BYTES;
#pragma unroll
        for (int ks = 0; ks < 2; ks++) {
            uint32_t ua[4][4];
#pragma unroll
            for (int i = 0; i < 4; i++) ldm_x4(ua[i], stage + (a_off[i] ^ (ks * 32)));
#pragma unroll
            for (int p = 0; p < 4; p++) {
                uint32_t ub[4];
                ldm_x4(ub, stage + (b_off[p] ^ (ks * 32)));
#pragma unroll
                for (int i = 0; i < 4; i++) {
                    imma(acc[i][2 * p],     ua[i], ub);
                    imma(acc[i][2 * p + 1], ua[i], ub + 2);
                }
            }
        }
        slot++; if (slot == STAGES) slot = 0;
    }

    // Epilogue: scale by s[m]*wscale and store
    float ws = g_wscale;
#pragma unroll
    for (int i = 0; i < 4; i++) {
        int row0 = pid_m * BM + WM + 16 * i + (lane >> 2);
        float s0 = g_sx[row0] * ws;
        float s1 = g_sx[row0 + 8] * ws;
        float* r0 = out + (size_t)row0 * N_DIM + pid_n * BN + WN;
        float* r1 = r0 + (size_t)8 * N_DIM;
#pragma unroll
        for (int j = 0; j < 8; j++) {
            int col = 8 * j + 2 * (lane & 3);
            float2 v0 = make_float2(acc[i][j][0] * s0, acc[i][j][1] * s0);
            float2 v1 = make_float2(acc[i][j][2] * s1, acc[i][j][3] * s1);
            *reinterpret_cast<float2*>(r0 + col) = v0;
            *reinterpret_cast<float2*>(r1 + col) = v1;
        }
    }
}

// ============================================================================
// Launch
// ============================================================================
extern "C" void kernel_launch(void* const* d_in, const int* in_sizes, int n_in,
                              void* d_out, int out_size) {
    const float* x = (const float*)d_in[0];
    const float* w = (const float*)d_in[1];
    if (n_in >= 2 && in_sizes[0] == 67108864) { // defensive: identify by size
        w = (const float*)d_in[0];
        x = (const float*)d_in[1];
    }
    float* out = (float*)d_out;

    cudaFuncSetAttribute(k_gemm, cudaFuncAttributeMaxDynamicSharedMemorySize, GEMM_SMEM);

    k_wabs<<<2048, 256>>>(w);
    k_wscale<<<1, 256>>>();
    k_wquant<<<16384, 256>>>(w);
    k_xquant<<<M_DIM, 128>>>(x);
    k_gemm<<<(M_DIM / BM) * (N_DIM / BN), 256, GEMM_SMEM>>>(out);
}

// round 4
// speedup vs baseline: 2.8306x; 2.8306x over previous
#include <cuda_runtime.h>
#include <cuda_bf16.h>
#include <stdint.h>

// ============================================================================
// Problem dims
// ============================================================================
#define M_DIM 8192       // 4 * 2048 tokens
#define K_DIM 4096       // in_features
#define N_DIM 16384      // out_features

// GEMM tiling (bf16 path)
#define BM 128
#define BN 256
#define BK 64                          // bf16 K elements per chunk = 128 B/row
#define NKC (K_DIM / BK)               // 64 chunks
#define STAGES 4
#define ROWB 128                       // bytes per SMEM row
#define STAGE_BYTES ((BM + BN) * ROWB) // 49152
#define GEMM_SMEM (STAGES * STAGE_BYTES) // 196608
#define K_BYTES (K_DIM * 2)            // global row stride in bytes

// ============================================================================
// Scratch (static device memory — no allocations allowed)
// ============================================================================
__device__ __align__(128) __nv_bfloat16 g_xq[(size_t)M_DIM * K_DIM]; // 64 MB
__device__ __align__(128) __nv_bfloat16 g_wt[(size_t)N_DIM * K_DIM]; // 128 MB
__device__ float  g_sx[M_DIM];
__device__ double g_partial[2048];
__device__ float  g_wscale;

// ============================================================================
// PTX helpers (base sm ISA only — no tcgen05, no arch-specific features)
// ============================================================================
__device__ __forceinline__ uint32_t smem_u32(const void* p) {
    uint32_t a;
    asm("{ .reg .u64 t; cvta.to.shared.u64 t, %1; cvt.u32.u64 %0, t; }" : "=r"(a) : "l"(p));
    return a;
}
__device__ __forceinline__ void cp16(uint32_t dst, const void* src) {
    asm volatile("cp.async.cg.shared.global [%0], [%1], 16;\n" :: "r"(dst), "l"(src) : "memory");
}
__device__ __forceinline__ void cp_commit() { asm volatile("cp.async.commit_group;" ::: "memory"); }
__device__ __forceinline__ void cp_wait2()  { asm volatile("cp.async.wait_group 2;" ::: "memory"); }
__device__ __forceinline__ void cp_wait1()  { asm volatile("cp.async.wait_group 1;" ::: "memory"); }
__device__ __forceinline__ void cp_wait0()  { asm volatile("cp.async.wait_group 0;" ::: "memory"); }

__device__ __forceinline__ void ldm_x4(uint32_t* r, uint32_t addr) {
    asm volatile("ldmatrix.sync.aligned.m8n8.x4.shared.b16 {%0,%1,%2,%3}, [%4];"
                 : "=r"(r[0]), "=r"(r[1]), "=r"(r[2]), "=r"(r[3]) : "r"(addr));
}
// bf16 HMMA with fp32 accumulation — hardware tensor path on sm_103 (legacy
// integer mma is ALU-emulated; fp path is not).
__device__ __forceinline__ void hmma(float* c, const uint32_t* a, const uint32_t* b) {
    asm volatile("mma.sync.aligned.m16n8k16.row.col.f32.bf16.bf16.f32 "
                 "{%0,%1,%2,%3}, {%4,%5,%6,%7}, {%8,%9}, {%0,%1,%2,%3};"
                 : "+f"(c[0]), "+f"(c[1]), "+f"(c[2]), "+f"(c[3])
                 : "r"(a[0]), "r"(a[1]), "r"(a[2]), "r"(a[3]), "r"(b[0]), "r"(b[1]));
}

// SW128 swizzle: 16B granule offset c (bits 4-6) XORed with (row&7)<<4.
// k-step offsets compose by XOR (k bits live inside the swizzled field).
__device__ __forceinline__ uint32_t swz(int row, int c) {
    return (uint32_t)(row * ROWB + (c ^ ((row & 7) << 4)));
}

// ============================================================================
// Kernel 1: |w| partial sums. grid 2048 x 256.
// ============================================================================
__global__ void k_wabs(const float* __restrict__ w) {
    int tid = threadIdx.x;
    const float4* wp = reinterpret_cast<const float4*>(w) + (size_t)blockIdx.x * 8192;
    float ssum = 0.f;
#pragma unroll
    for (int i = 0; i < 32; i++) {
        float4 v = wp[tid + i * 256];
        ssum += fabsf(v.x) + fabsf(v.y) + fabsf(v.z) + fabsf(v.w);
    }
#pragma unroll
    for (int o = 16; o > 0; o >>= 1) ssum += __shfl_xor_sync(0xffffffffu, ssum, o);
    __shared__ double wsum[8];
    if ((tid & 31) == 0) wsum[tid >> 5] = (double)ssum;
    __syncthreads();
    if (tid == 0) {
        double t = 0.0;
#pragma unroll
        for (int i = 0; i < 8; i++) t += wsum[i];
        g_partial[blockIdx.x] = t;
    }
}

// Kernel 2: final reduce -> wscale
__global__ void k_wscale(void) {
    int tid = threadIdx.x; // 256
    double t = 0.0;
#pragma unroll
    for (int i = 0; i < 8; i++) t += g_partial[tid + i * 256];
    __shared__ double sm[256];
    sm[tid] = t;
    __syncthreads();
    if (tid == 0) {
        double a = 0.0;
        for (int i = 0; i < 256; i++) a += sm[i];
        float mean = (float)(a / 67108864.0);
        g_wscale = fmaxf(mean, 1e-5f);
    }
}

// Kernel 3: ternarize weights -> bf16 {-1,0,+1}. grid 16384 x 256.
__global__ void k_wquant(const float* __restrict__ w) {
    float half = 0.5f * g_wscale;
    size_t base = (size_t)blockIdx.x * 1024 + threadIdx.x; // float4 units
    const float4* wp = reinterpret_cast<const float4*>(w);
    uint2* o = reinterpret_cast<uint2*>(g_wt);
#pragma unroll
    for (int i = 0; i < 4; i++) {
        size_t idx = base + (size_t)i * 256;
        float4 v = wp[idx];
        // ternary bf16 bits: +1 = 0x3F80, -1 = 0xBF80, 0 = 0
        uint32_t a = (v.x > half) ? 0x3F80u : ((v.x < -half) ? 0xBF80u : 0u);
        uint32_t b = (v.y > half) ? 0x3F80u : ((v.y < -half) ? 0xBF80u : 0u);
        uint32_t c = (v.z > half) ? 0x3F80u : ((v.z < -half) ? 0xBF80u : 0u);
        uint32_t d = (v.w > half) ? 0x3F80u : ((v.w < -half) ? 0xBF80u : 0u);
        o[idx] = make_uint2(a | (b << 16), c | (d << 16));
    }
}

// Kernel 4: per-token int4 quant of x -> bf16 ints + s[token]. grid 8192 x 128.
__global__ void k_xquant(const float* __restrict__ x) {
    int token = blockIdx.x;
    int tid = threadIdx.x;
    const float4* xin = reinterpret_cast<const float4*>(x + (size_t)token * K_DIM);
    float4 v[8];
    float amax = 0.f;
#pragma unroll
    for (int i = 0; i < 8; i++) {
        v[i] = xin[tid + i * 128];
        amax = fmaxf(amax, fmaxf(fmaxf(fabsf(v[i].x), fabsf(v[i].y)),
                                 fmaxf(fabsf(v[i].z), fabsf(v[i].w))));
    }
#pragma unroll
    for (int o = 16; o > 0; o >>= 1) amax = fmaxf(amax, __shfl_xor_sync(0xffffffffu, amax, o));
    __shared__ float wmax[4];
    if ((tid & 31) == 0) wmax[tid >> 5] = amax;
    __syncthreads();
    amax = fmaxf(fmaxf(wmax[0], wmax[1]), fmaxf(wmax[2], wmax[3]));
    float s = __fdiv_rn(fmaxf(amax, 1e-5f), 7.0f);
    float inv = __fdiv_rn(1.0f, s);
    if (tid == 0) g_sx[token] = s;
    uint2* qo = reinterpret_cast<uint2*>(g_xq + (size_t)token * K_DIM);
#pragma unroll
    for (int i = 0; i < 8; i++) {
        float a = fminf(fmaxf(rintf(v[i].x * inv), -8.f), 7.f);
        float b = fminf(fmaxf(rintf(v[i].y * inv), -8.f), 7.f);
        float c = fminf(fmaxf(rintf(v[i].z * inv), -8.f), 7.f);
        float d = fminf(fmaxf(rintf(v[i].w * inv), -8.f), 7.f);
        // small integers are exact in bf16
        uint32_t ab = ((uint32_t)__bfloat16_as_ushort(__float2bfloat16(a)))
                    | ((uint32_t)__bfloat16_as_ushort(__float2bfloat16(b)) << 16);
        uint32_t cd = ((uint32_t)__bfloat16_as_ushort(__float2bfloat16(c)))
                    | ((uint32_t)__bfloat16_as_ushort(__float2bfloat16(d)) << 16);
        qo[tid + i * 128] = make_uint2(ab, cd);
    }
}

// ============================================================================
// Kernel 5: bf16 HMMA GEMM. BM=128 x BN=256 x BK=64, 4-stage cp.async,
// 8 warps of 64x64, ldmatrix fragment loads, SW128 swizzle.
// ============================================================================
__device__ __forceinline__ void load_chunk(uint32_t stage, const __nv_bfloat16* Abase,
                                           const __nv_bfloat16* Bbase, int kc, int tid) {
    uint32_t a_s = stage;
    uint32_t b_s = stage + BM * ROWB;
    const char* ag = reinterpret_cast<const char*>(Abase) + kc * ROWB;
    const char* bg = reinterpret_cast<const char*>(Bbase) + kc * ROWB;
    // A: 128 rows x 8 granules = 1024, 4 per thread
#pragma unroll
    for (int i = 0; i < 4; i++) {
        int g = tid + 256 * i;
        int r = g >> 3, c = (g & 7) * 16;
        cp16(a_s + swz(r, c), ag + (size_t)r * K_BYTES + c);
    }
    // B: 256 rows x 8 granules = 2048, 8 per thread
#pragma unroll
    for (int i = 0; i < 8; i++) {
        int g = tid + 256 * i;
        int r = g >> 3, c = (g & 7) * 16;
        cp16(b_s + swz(r, c), bg + (size_t)r * K_BYTES + c);
    }
    cp_commit();
}

__global__ void __launch_bounds__(256, 1) k_gemm(float* __restrict__ out) {
    extern __shared__ char smem[];
    uint32_t sb = smem_u32(smem);
    int tid = threadIdx.x;
    int wid = tid >> 5;
    int lane = tid & 31;

    // Grouped rasterization for L2 reuse
    const int num_pid_n = N_DIM / BN; // 64
    const int GROUP = 8;
    int pid = blockIdx.x;
    int npg = GROUP * num_pid_n;
    int group_id = pid / npg;
    int first_m = group_id * GROUP;
    int pid_m = first_m + ((pid % npg) % GROUP);
    int pid_n = (pid % npg) / GROUP;

    const __nv_bfloat16* Abase = g_xq + (size_t)pid_m * BM * K_DIM;
    const __nv_bfloat16* Bbase = g_wt + (size_t)pid_n * BN * K_DIM;

    int WM = (wid >> 2) * 64;  // warp m offset (0 or 64)
    int WN = (wid & 3) * 64;   // warp n offset (0,64,128,192)

    float acc[4][8][4];
#pragma unroll
    for (int i = 0; i < 4; i++)
#pragma unroll
        for (int j = 0; j < 8; j++)
#pragma unroll
            for (int q = 0; q < 4; q++) acc[i][j][q] = 0.f;

    // ldmatrix base offsets (k-step selects bits 5-6 by XOR)
    uint32_t a_off[4];
#pragma unroll
    for (int i = 0; i < 4; i++) {
        int row = WM + 16 * i + (lane & 15);
        a_off[i] = swz(row, ((lane >> 4) & 1) * 16);
    }
    uint32_t b_off[4];
#pragma unroll
    for (int p = 0; p < 4; p++) {
        int n = WN + 16 * p + (lane & 7) + ((lane >> 4) & 1) * 8;
        b_off[p] = (uint32_t)(BM * ROWB) + swz(n, ((lane >> 3) & 1) * 16);
    }

    // Prologue: fill 3 of 4 stages
    load_chunk(sb + 0 * STAGE_BYTES, Abase, Bbase, 0, tid);
    load_chunk(sb + 1 * STAGE_BYTES, Abase, Bbase, 1, tid);
    load_chunk(sb + 2 * STAGE_BYTES, Abase, Bbase, 2, tid);

#pragma unroll 1
    for (int kc = 0; kc < NKC; kc++) {
        if (kc < NKC - 2) cp_wait2();
        else if (kc == NKC - 2) cp_wait1();
        else cp_wait0();
        __syncthreads();
        // Refill the slot freed last iteration
        if (kc + 3 < NKC)
            load_chunk(sb + ((kc + 3) & 3) * STAGE_BYTES, Abase, Bbase, kc + 3, tid);
        uint32_t stage = sb + (kc & 3) * STAGE_BYTES;
#pragma unroll
        for (int ks = 0; ks < 4; ks++) {
            uint32_t kx = (uint32_t)(ks * 32);
            uint32_t ua[4][4];
#pragma unroll
            for (int i = 0; i < 4; i++) ldm_x4(ua[i], stage + (a_off[i] ^ kx));
#pragma unroll
            for (int p = 0; p < 4; p++) {
                uint32_t ub[4];
                ldm_x4(ub, stage + (b_off[p] ^ kx));
#pragma unroll
                for (int i = 0; i < 4; i++) {
                    hmma(acc[i][2 * p],     ua[i], ub);
                    hmma(acc[i][2 * p + 1], ua[i], ub + 2);
                }
            }
        }
    }

    // Epilogue: scale by s[m]*wscale and store
    float ws = g_wscale;
#pragma unroll
    for (int i = 0; i < 4; i++) {
        int row0 = pid_m * BM + WM + 16 * i + (lane >> 2);
        float s0 = g_sx[row0] * ws;
        float s1 = g_sx[row0 + 8] * ws;
        float* r0 = out + (size_t)row0 * N_DIM + pid_n * BN + WN;
        float* r1 = r0 + (size_t)8 * N_DIM;
#pragma unroll
        for (int j = 0; j < 8; j++) {
            int col = 8 * j + 2 * (lane & 3);
            float2 v0 = make_float2(acc[i][j][0] * s0, acc[i][j][1] * s0);
            float2 v1 = make_float2(acc[i][j][2] * s1, acc[i][j][3] * s1);
            *reinterpret_cast<float2*>(r0 + col) = v0;
            *reinterpret_cast<float2*>(r1 + col) = v1;
        }
    }
}

// ============================================================================
// Launch
// ============================================================================
extern "C" void kernel_launch(void* const* d_in, const int* in_sizes, int n_in,
                              void* d_out, int out_size) {
    const float* x = (const float*)d_in[0];
    const float* w = (const float*)d_in[1];
    if (n_in >= 2 && in_sizes[0] == 67108864) { // defensive: identify by size
        w = (const float*)d_in[0];
        x = (const float*)d_in[1];
    }
    float* out = (float*)d_out;

    cudaFuncSetAttribute(k_gemm, cudaFuncAttributeMaxDynamicSharedMemorySize, GEMM_SMEM);

    k_wabs<<<2048, 256>>>(w);
    k_wscale<<<1, 256>>>();
    k_wquant<<<16384, 256>>>(w);
    k_xquant<<<M_DIM, 128>>>(x);
    k_gemm<<<(M_DIM / BM) * (N_DIM / BN), 256, GEMM_SMEM>>>(out);
}

// round 5
// speedup vs baseline: 3.0631x; 1.0821x over previous
#include <cuda_runtime.h>
#include <cuda_bf16.h>
#include <stdint.h>

// ============================================================================
// Problem dims
// ============================================================================
#define M_DIM 8192       // 4 * 2048 tokens
#define K_DIM 4096       // in_features
#define N_DIM 16384      // out_features

// GEMM tiling (bf16 path)
#define BM 128
#define BN 256
#define BK 64                          // bf16 K elements per chunk = 128 B/row
#define NKC (K_DIM / BK)               // 64 chunks
#define STAGES 4
#define ROWB 128                       // bytes per SMEM row
#define STAGE_BYTES ((BM + BN) * ROWB) // 49152
#define GEMM_SMEM (STAGES * STAGE_BYTES) // 196608
#define K_BYTES (K_DIM * 2)            // global row stride in bytes
#define GTHREADS 512

// ============================================================================
// Scratch (static device memory — no allocations allowed)
// ============================================================================
__device__ __align__(128) __nv_bfloat16 g_xq[(size_t)M_DIM * K_DIM]; // 64 MB
__device__ __align__(128) __nv_bfloat16 g_wt[(size_t)N_DIM * K_DIM]; // 128 MB
__device__ float  g_sx[M_DIM];
__device__ double g_partial[2048];
__device__ float  g_wscale;
__device__ unsigned int g_ctr = 0;

// ============================================================================
// PTX helpers (base sm ISA only — no tcgen05, no arch-specific features)
// ============================================================================
__device__ __forceinline__ uint32_t smem_u32(const void* p) {
    uint32_t a;
    asm("{ .reg .u64 t; cvta.to.shared.u64 t, %1; cvt.u32.u64 %0, t; }" : "=r"(a) : "l"(p));
    return a;
}
__device__ __forceinline__ void cp16(uint32_t dst, const void* src) {
    asm volatile("cp.async.cg.shared.global [%0], [%1], 16;\n" :: "r"(dst), "l"(src) : "memory");
}
__device__ __forceinline__ void cp_commit() { asm volatile("cp.async.commit_group;" ::: "memory"); }
__device__ __forceinline__ void cp_wait2()  { asm volatile("cp.async.wait_group 2;" ::: "memory"); }
__device__ __forceinline__ void cp_wait1()  { asm volatile("cp.async.wait_group 1;" ::: "memory"); }
__device__ __forceinline__ void cp_wait0()  { asm volatile("cp.async.wait_group 0;" ::: "memory"); }

__device__ __forceinline__ void ldm_x4(uint32_t* r, uint32_t addr) {
    asm volatile("ldmatrix.sync.aligned.m8n8.x4.shared.b16 {%0,%1,%2,%3}, [%4];"
                 : "=r"(r[0]), "=r"(r[1]), "=r"(r[2]), "=r"(r[3]) : "r"(addr));
}
// bf16 HMMA with fp32 accumulation — hardware tensor path on sm_103 (legacy
// integer mma is ALU-emulated; fp path is not).
__device__ __forceinline__ void hmma(float* c, const uint32_t* a, const uint32_t* b) {
    asm volatile("mma.sync.aligned.m16n8k16.row.col.f32.bf16.bf16.f32 "
                 "{%0,%1,%2,%3}, {%4,%5,%6,%7}, {%8,%9}, {%0,%1,%2,%3};"
                 : "+f"(c[0]), "+f"(c[1]), "+f"(c[2]), "+f"(c[3])
                 : "r"(a[0]), "r"(a[1]), "r"(a[2]), "r"(a[3]), "r"(b[0]), "r"(b[1]));
}

// SW128 swizzle: 16B granule offset c (bits 4-6) XORed with (row&7)<<4.
// k-step offsets compose by XOR (k bits live inside the swizzled field).
__device__ __forceinline__ uint32_t swz(int row, int c) {
    return (uint32_t)(row * ROWB + (c ^ ((row & 7) << 4)));
}

// ============================================================================
// Kernel 1: |w| mean via partial sums + deterministic last-block reduce.
// grid 2048 x 256, each block covers 32768 floats.
// ============================================================================
__global__ void k_wabs(const float* __restrict__ w) {
    int tid = threadIdx.x;
    const float4* wp = reinterpret_cast<const float4*>(w) + (size_t)blockIdx.x * 8192;
    float ssum = 0.f;
#pragma unroll
    for (int i = 0; i < 32; i++) {
        float4 v = wp[tid + i * 256];
        ssum += fabsf(v.x) + fabsf(v.y) + fabsf(v.z) + fabsf(v.w);
    }
#pragma unroll
    for (int o = 16; o > 0; o >>= 1) ssum += __shfl_xor_sync(0xffffffffu, ssum, o);
    __shared__ double wsum[8];
    __shared__ int is_last;
    if ((tid & 31) == 0) wsum[tid >> 5] = (double)ssum;
    __syncthreads();
    if (tid == 0) {
        double t = 0.0;
#pragma unroll
        for (int i = 0; i < 8; i++) t += wsum[i];
        g_partial[blockIdx.x] = t;
        __threadfence();
        unsigned int prev = atomicAdd(&g_ctr, 1u);
        is_last = (prev == gridDim.x - 1);
    }
    __syncthreads();
    if (!is_last) return;
    // Last block: deterministic fixed-order reduction of all 2048 partials.
    __threadfence();
    double t = 0.0;
#pragma unroll
    for (int i = 0; i < 8; i++) t += g_partial[tid + i * 256];
    __shared__ double sm[256];
    sm[tid] = t;
    __syncthreads();
    if (tid == 0) {
        double a = 0.0;
        for (int i = 0; i < 256; i++) a += sm[i];
        float mean = (float)(a / 67108864.0);
        g_wscale = fmaxf(mean, 1e-5f);
        g_ctr = 0;  // reset for next graph replay
    }
}

// Kernel 2: ternarize weights -> bf16 {-1,0,+1}. grid 16384 x 256.
__global__ void k_wquant(const float* __restrict__ w) {
    float half = 0.5f * g_wscale;
    size_t base = (size_t)blockIdx.x * 1024 + threadIdx.x; // float4 units
    const float4* wp = reinterpret_cast<const float4*>(w);
    uint2* o = reinterpret_cast<uint2*>(g_wt);
#pragma unroll
    for (int i = 0; i < 4; i++) {
        size_t idx = base + (size_t)i * 256;
        float4 v = wp[idx];
        // ternary bf16 bits: +1 = 0x3F80, -1 = 0xBF80, 0 = 0
        uint32_t a = (v.x > half) ? 0x3F80u : ((v.x < -half) ? 0xBF80u : 0u);
        uint32_t b = (v.y > half) ? 0x3F80u : ((v.y < -half) ? 0xBF80u : 0u);
        uint32_t c = (v.z > half) ? 0x3F80u : ((v.z < -half) ? 0xBF80u : 0u);
        uint32_t d = (v.w > half) ? 0x3F80u : ((v.w < -half) ? 0xBF80u : 0u);
        o[idx] = make_uint2(a | (b << 16), c | (d << 16));
    }
}

// Kernel 3: per-token int4 quant of x -> bf16 ints + s[token]. grid 8192 x 128.
__global__ void k_xquant(const float* __restrict__ x) {
    int token = blockIdx.x;
    int tid = threadIdx.x;
    const float4* xin = reinterpret_cast<const float4*>(x + (size_t)token * K_DIM);
    float4 v[8];
    float amax = 0.f;
#pragma unroll
    for (int i = 0; i < 8; i++) {
        v[i] = xin[tid + i * 128];
        amax = fmaxf(amax, fmaxf(fmaxf(fabsf(v[i].x), fabsf(v[i].y)),
                                 fmaxf(fabsf(v[i].z), fabsf(v[i].w))));
    }
#pragma unroll
    for (int o = 16; o > 0; o >>= 1) amax = fmaxf(amax, __shfl_xor_sync(0xffffffffu, amax, o));
    __shared__ float wmax[4];
    if ((tid & 31) == 0) wmax[tid >> 5] = amax;
    __syncthreads();
    amax = fmaxf(fmaxf(wmax[0], wmax[1]), fmaxf(wmax[2], wmax[3]));
    float s = __fdiv_rn(fmaxf(amax, 1e-5f), 7.0f);
    float inv = __fdiv_rn(1.0f, s);
    if (tid == 0) g_sx[token] = s;
    uint2* qo = reinterpret_cast<uint2*>(g_xq + (size_t)token * K_DIM);
#pragma unroll
    for (int i = 0; i < 8; i++) {
        float a = fminf(fmaxf(rintf(v[i].x * inv), -8.f), 7.f);
        float b = fminf(fmaxf(rintf(v[i].y * inv), -8.f), 7.f);
        float c = fminf(fmaxf(rintf(v[i].z * inv), -8.f), 7.f);
        float d = fminf(fmaxf(rintf(v[i].w * inv), -8.f), 7.f);
        // small integers are exact in bf16
        uint32_t ab = ((uint32_t)__bfloat16_as_ushort(__float2bfloat16(a)))
                    | ((uint32_t)__bfloat16_as_ushort(__float2bfloat16(b)) << 16);
        uint32_t cd = ((uint32_t)__bfloat16_as_ushort(__float2bfloat16(c)))
                    | ((uint32_t)__bfloat16_as_ushort(__float2bfloat16(d)) << 16);
        qo[tid + i * 128] = make_uint2(ab, cd);
    }
}

// ============================================================================
// Kernel 4: bf16 HMMA GEMM. BM=128 x BN=256 x BK=64, 4-stage cp.async,
// 512 threads / 16 warps of 64x32, ldmatrix fragment loads, SW128 swizzle.
// ============================================================================
__device__ __forceinline__ void load_chunk(uint32_t stage, const __nv_bfloat16* Abase,
                                           const __nv_bfloat16* Bbase, int kc, int tid) {
    uint32_t a_s = stage;
    uint32_t b_s = stage + BM * ROWB;
    const char* ag = reinterpret_cast<const char*>(Abase) + kc * ROWB;
    const char* bg = reinterpret_cast<const char*>(Bbase) + kc * ROWB;
    // A: 128 rows x 8 granules = 1024, 2 per thread
#pragma unroll
    for (int i = 0; i < 2; i++) {
        int g = tid + GTHREADS * i;
        int r = g >> 3, c = (g & 7) * 16;
        cp16(a_s + swz(r, c), ag + (size_t)r * K_BYTES + c);
    }
    // B: 256 rows x 8 granules = 2048, 4 per thread
#pragma unroll
    for (int i = 0; i < 4; i++) {
        int g = tid + GTHREADS * i;
        int r = g >> 3, c = (g & 7) * 16;
        cp16(b_s + swz(r, c), bg + (size_t)r * K_BYTES + c);
    }
    cp_commit();
}

__global__ void __launch_bounds__(GTHREADS, 1) k_gemm(float* __restrict__ out) {
    extern __shared__ char smem[];
    uint32_t sb = smem_u32(smem);
    int tid = threadIdx.x;
    int wid = tid >> 5;
    int lane = tid & 31;

    // Grouped rasterization for L2 reuse
    const int num_pid_n = N_DIM / BN; // 64
    const int GROUP = 8;
    int pid = blockIdx.x;
    int npg = GROUP * num_pid_n;
    int group_id = pid / npg;
    int first_m = group_id * GROUP;
    int pid_m = first_m + ((pid % npg) % GROUP);
    int pid_n = (pid % npg) / GROUP;

    const __nv_bfloat16* Abase = g_xq + (size_t)pid_m * BM * K_DIM;
    const __nv_bfloat16* Bbase = g_wt + (size_t)pid_n * BN * K_DIM;

    int WM = (wid & 1) * 64;   // warp m offset (0 or 64)
    int WN = (wid >> 1) * 32;  // warp n offset (0,32,...,224)

    float acc[4][4][4];
#pragma unroll
    for (int i = 0; i < 4; i++)
#pragma unroll
        for (int j = 0; j < 4; j++)
#pragma unroll
            for (int q = 0; q < 4; q++) acc[i][j][q] = 0.f;

    // ldmatrix base offsets (k-step selects bits 5-6 by XOR)
    uint32_t a_off[4];
#pragma unroll
    for (int i = 0; i < 4; i++) {
        int row = WM + 16 * i + (lane & 15);
        a_off[i] = swz(row, ((lane >> 4) & 1) * 16);
    }
    uint32_t b_off[2];
#pragma unroll
    for (int p = 0; p < 2; p++) {
        int n = WN + 16 * p + (lane & 7) + ((lane >> 4) & 1) * 8;
        b_off[p] = (uint32_t)(BM * ROWB) + swz(n, ((lane >> 3) & 1) * 16);
    }

    // Prologue: fill 3 of 4 stages
    load_chunk(sb + 0 * STAGE_BYTES, Abase, Bbase, 0, tid);
    load_chunk(sb + 1 * STAGE_BYTES, Abase, Bbase, 1, tid);
    load_chunk(sb + 2 * STAGE_BYTES, Abase, Bbase, 2, tid);

#pragma unroll 1
    for (int kc = 0; kc < NKC; kc++) {
        if (kc < NKC - 2) cp_wait2();
        else if (kc == NKC - 2) cp_wait1();
        else cp_wait0();
        __syncthreads();
        // Refill the slot freed last iteration
        if (kc + 3 < NKC)
            load_chunk(sb + ((kc + 3) & 3) * STAGE_BYTES, Abase, Bbase, kc + 3, tid);
        uint32_t stage = sb + (kc & 3) * STAGE_BYTES;
#pragma unroll
        for (int ks = 0; ks < 4; ks++) {
            uint32_t kx = (uint32_t)(ks * 32);
            uint32_t ua[4][4], ub[2][4];
#pragma unroll
            for (int i = 0; i < 4; i++) ldm_x4(ua[i], stage + (a_off[i] ^ kx));
#pragma unroll
            for (int p = 0; p < 2; p++) ldm_x4(ub[p], stage + (b_off[p] ^ kx));
#pragma unroll
            for (int p = 0; p < 2; p++)
#pragma unroll
                for (int i = 0; i < 4; i++) {
                    hmma(acc[i][2 * p],     ua[i], ub[p]);
                    hmma(acc[i][2 * p + 1], ua[i], ub[p] + 2);
                }
        }
    }

    // Epilogue: scale by s[m]*wscale and store
    float ws = g_wscale;
#pragma unroll
    for (int i = 0; i < 4; i++) {
        int row0 = pid_m * BM + WM + 16 * i + (lane >> 2);
        float s0 = g_sx[row0] * ws;
        float s1 = g_sx[row0 + 8] * ws;
        float* r0 = out + (size_t)row0 * N_DIM + pid_n * BN + WN;
        float* r1 = r0 + (size_t)8 * N_DIM;
#pragma unroll
        for (int j = 0; j < 4; j++) {
            int col = 8 * j + 2 * (lane & 3);
            float2 v0 = make_float2(acc[i][j][0] * s0, acc[i][j][1] * s0);
            float2 v1 = make_float2(acc[i][j][2] * s1, acc[i][j][3] * s1);
            *reinterpret_cast<float2*>(r0 + col) = v0;
            *reinterpret_cast<float2*>(r1 + col) = v1;
        }
    }
}

// ============================================================================
// Launch
// ============================================================================
extern "C" void kernel_launch(void* const* d_in, const int* in_sizes, int n_in,
                              void* d_out, int out_size) {
    const float* x = (const float*)d_in[0];
    const float* w = (const float*)d_in[1];
    if (n_in >= 2 && in_sizes[0] == 67108864) { // defensive: identify by size
        w = (const float*)d_in[0];
        x = (const float*)d_in[1];
    }
    float* out = (float*)d_out;

    cudaFuncSetAttribute(k_gemm, cudaFuncAttributeMaxDynamicSharedMemorySize, GEMM_SMEM);

    k_wabs<<<2048, 256>>>(w);        // includes deterministic final reduce
    k_wquant<<<16384, 256>>>(w);
    k_xquant<<<M_DIM, 128>>>(x);
    k_gemm<<<(M_DIM / BM) * (N_DIM / BN), GTHREADS, GEMM_SMEM>>>(out);
}

// round 8
// speedup vs baseline: 3.2914x; 1.0745x over previous
#include <cuda_runtime.h>
#include <cuda_bf16.h>
#include <stdint.h>

// ============================================================================
// Problem dims
// ============================================================================
#define M_DIM 8192       // 4 * 2048 tokens
#define K_DIM 4096       // in_features
#define N_DIM 16384      // out_features

// GEMM tiling (bf16 path) — 2 CTAs/SM for barrier-bubble overlap
#define BM 128
#define BN 128
#define BK 64                          // bf16 K elements per chunk = 128 B/row
#define NKC (K_DIM / BK)               // 64 chunks
#define STAGES 3
#define ROWB 128                       // bytes per SMEM row
#define STAGE_BYTES ((BM + BN) * ROWB) // 32768
#define GEMM_SMEM (STAGES * STAGE_BYTES) // 98304 -> 2 CTAs per SM
#define K_BYTES (K_DIM * 2)            // global row stride in bytes
#define GTHREADS 256

// ============================================================================
// Scratch (static device memory — no allocations allowed)
// ============================================================================
__device__ __align__(128) __nv_bfloat16 g_xq[(size_t)M_DIM * K_DIM]; // 64 MB
__device__ __align__(128) __nv_bfloat16 g_wt[(size_t)N_DIM * K_DIM]; // 128 MB
__device__ float  g_sx[M_DIM];
__device__ double g_partial[2048];
__device__ float  g_wscale;
__device__ unsigned int g_ctr = 0;

// ============================================================================
// PTX helpers (base sm ISA only — no tcgen05)
// ============================================================================
__device__ __forceinline__ uint32_t smem_u32(const void* p) {
    uint32_t a;
    asm("{ .reg .u64 t; cvta.to.shared.u64 t, %1; cvt.u32.u64 %0, t; }" : "=r"(a) : "l"(p));
    return a;
}
__device__ __forceinline__ void cp16(uint32_t dst, const void* src) {
    asm volatile("cp.async.cg.shared.global [%0], [%1], 16;\n" :: "r"(dst), "l"(src) : "memory");
}
__device__ __forceinline__ void cp_commit() { asm volatile("cp.async.commit_group;" ::: "memory"); }
__device__ __forceinline__ void cp_wait1()  { asm volatile("cp.async.wait_group 1;" ::: "memory"); }
__device__ __forceinline__ void cp_wait0()  { asm volatile("cp.async.wait_group 0;" ::: "memory"); }

__device__ __forceinline__ void ldm_x4(uint32_t* r, uint32_t addr) {
    asm volatile("ldmatrix.sync.aligned.m8n8.x4.shared.b16 {%0,%1,%2,%3}, [%4];"
                 : "=r"(r[0]), "=r"(r[1]), "=r"(r[2]), "=r"(r[3]) : "r"(addr));
}
// bf16 HMMA with fp32 accumulation — hardware tensor path (legacy int mma is
// ALU-emulated on sm_103; fp path runs on the tensor pipe at ~1024 MAC/cyc/SM).
__device__ __forceinline__ void hmma(float* c, const uint32_t* a, const uint32_t* b) {
    asm volatile("mma.sync.aligned.m16n8k16.row.col.f32.bf16.bf16.f32 "
                 "{%0,%1,%2,%3}, {%4,%5,%6,%7}, {%8,%9}, {%0,%1,%2,%3};"
                 : "+f"(c[0]), "+f"(c[1]), "+f"(c[2]), "+f"(c[3])
                 : "r"(a[0]), "r"(a[1]), "r"(a[2]), "r"(a[3]), "r"(b[0]), "r"(b[1]));
}

// SW128 swizzle: 16B granule offset c (bits 4-6) XORed with (row&7)<<4.
// k-step offsets compose by XOR (k bits live inside the swizzled field).
__device__ __forceinline__ uint32_t swz(int row, int c) {
    return (uint32_t)(row * ROWB + (c ^ ((row & 7) << 4)));
}

// ============================================================================
// Kernel 1: |w| mean via partial sums + deterministic last-block reduce.
// grid 2048 x 256, each block covers 32768 floats.
// ============================================================================
__global__ void k_wabs(const float* __restrict__ w) {
    int tid = threadIdx.x;
    const float4* wp = reinterpret_cast<const float4*>(w) + (size_t)blockIdx.x * 8192;
    float ssum = 0.f;
#pragma unroll
    for (int i = 0; i < 32; i++) {
        float4 v = wp[tid + i * 256];
        ssum += fabsf(v.x) + fabsf(v.y) + fabsf(v.z) + fabsf(v.w);
    }
#pragma unroll
    for (int o = 16; o > 0; o >>= 1) ssum += __shfl_xor_sync(0xffffffffu, ssum, o);
    __shared__ double wsum[8];
    __shared__ int is_last;
    if ((tid & 31) == 0) wsum[tid >> 5] = (double)ssum;
    __syncthreads();
    if (tid == 0) {
        double t = 0.0;
#pragma unroll
        for (int i = 0; i < 8; i++) t += wsum[i];
        g_partial[blockIdx.x] = t;
        __threadfence();
        unsigned int prev = atomicAdd(&g_ctr, 1u);
        is_last = (prev == gridDim.x - 1);
    }
    __syncthreads();
    if (!is_last) return;
    // Last block: deterministic fixed-order reduction of all 2048 partials.
    __threadfence();
    double t = 0.0;
#pragma unroll
    for (int i = 0; i < 8; i++) t += g_partial[tid + i * 256];
    __shared__ double sm[256];
    sm[tid] = t;
    __syncthreads();
    if (tid == 0) {
        double a = 0.0;
        for (int i = 0; i < 256; i++) a += sm[i];
        float mean = (float)(a / 67108864.0);
        g_wscale = fmaxf(mean, 1e-5f);
        g_ctr = 0;  // reset for next graph replay
    }
}

// Kernel 2: ternarize weights -> bf16 {-1,0,+1}. grid 16384 x 256.
__global__ void k_wquant(const float* __restrict__ w) {
    float half = 0.5f * g_wscale;
    size_t base = (size_t)blockIdx.x * 1024 + threadIdx.x; // float4 units
    const float4* wp = reinterpret_cast<const float4*>(w);
    uint2* o = reinterpret_cast<uint2*>(g_wt);
#pragma unroll
    for (int i = 0; i < 4; i++) {
        size_t idx = base + (size_t)i * 256;
        float4 v = wp[idx];
        // ternary bf16 bits: +1 = 0x3F80, -1 = 0xBF80, 0 = 0
        uint32_t a = (v.x > half) ? 0x3F80u : ((v.x < -half) ? 0xBF80u : 0u);
        uint32_t b = (v.y > half) ? 0x3F80u : ((v.y < -half) ? 0xBF80u : 0u);
        uint32_t c = (v.z > half) ? 0x3F80u : ((v.z < -half) ? 0xBF80u : 0u);
        uint32_t d = (v.w > half) ? 0x3F80u : ((v.w < -half) ? 0xBF80u : 0u);
        o[idx] = make_uint2(a | (b << 16), c | (d << 16));
    }
}

// Kernel 3: per-token int4 quant of x -> bf16 ints + s[token]. grid 8192 x 128.
__global__ void k_xquant(const float* __restrict__ x) {
    int token = blockIdx.x;
    int tid = threadIdx.x;
    const float4* xin = reinterpret_cast<const float4*>(x + (size_t)token * K_DIM);
    float4 v[8];
    float amax = 0.f;
#pragma unroll
    for (int i = 0; i < 8; i++) {
        v[i] = xin[tid + i * 128];
        amax = fmaxf(amax, fmaxf(fmaxf(fabsf(v[i].x), fabsf(v[i].y)),
                                 fmaxf(fabsf(v[i].z), fabsf(v[i].w))));
    }
#pragma unroll
    for (int o = 16; o > 0; o >>= 1) amax = fmaxf(amax, __shfl_xor_sync(0xffffffffu, amax, o));
    __shared__ float wmax[4];
    if ((tid & 31) == 0) wmax[tid >> 5] = amax;
    __syncthreads();
    amax = fmaxf(fmaxf(wmax[0], wmax[1]), fmaxf(wmax[2], wmax[3]));
    float s = __fdiv_rn(fmaxf(amax, 1e-5f), 7.0f);
    float inv = __fdiv_rn(1.0f, s);
    if (tid == 0) g_sx[token] = s;
    uint2* qo = reinterpret_cast<uint2*>(g_xq + (size_t)token * K_DIM);
#pragma unroll
    for (int i = 0; i < 8; i++) {
        float a = fminf(fmaxf(rintf(v[i].x * inv), -8.f), 7.f);
        float b = fminf(fmaxf(rintf(v[i].y * inv), -8.f), 7.f);
        float c = fminf(fmaxf(rintf(v[i].z * inv), -8.f), 7.f);
        float d = fminf(fmaxf(rintf(v[i].w * inv), -8.f), 7.f);
        // small integers are exact in bf16
        uint32_t ab = ((uint32_t)__bfloat16_as_ushort(__float2bfloat16(a)))
                    | ((uint32_t)__bfloat16_as_ushort(__float2bfloat16(b)) << 16);
        uint32_t cd = ((uint32_t)__bfloat16_as_ushort(__float2bfloat16(c)))
                    | ((uint32_t)__bfloat16_as_ushort(__float2bfloat16(d)) << 16);
        qo[tid + i * 128] = make_uint2(ab, cd);
    }
}

// ============================================================================
// Kernel 4: bf16 HMMA GEMM. BM=128 x BN=128 x BK=64, 3-stage cp.async,
// 256 threads / 8 warps of 64x32, 2 CTAs per SM.
// ============================================================================
__device__ __forceinline__ void load_chunk(uint32_t stage, const __nv_bfloat16* Abase,
                                           const __nv_bfloat16* Bbase, int kc, int tid) {
    uint32_t a_s = stage;
    uint32_t b_s = stage + BM * ROWB;
    const char* ag = reinterpret_cast<const char*>(Abase) + kc * ROWB;
    const char* bg = reinterpret_cast<const char*>(Bbase) + kc * ROWB;
    // A: 128 rows x 8 granules = 1024, 4 per thread
#pragma unroll
    for (int i = 0; i < 4; i++) {
        int g = tid + GTHREADS * i;
        int r = g >> 3, c = (g & 7) * 16;
        cp16(a_s + swz(r, c), ag + (size_t)r * K_BYTES + c);
    }
    // B: 128 rows x 8 granules = 1024, 4 per thread
#pragma unroll
    for (int i = 0; i < 4; i++) {
        int g = tid + GTHREADS * i;
        int r = g >> 3, c = (g & 7) * 16;
        cp16(b_s + swz(r, c), bg + (size_t)r * K_BYTES + c);
    }
    cp_commit();
}

__global__ void __launch_bounds__(GTHREADS, 2) k_gemm(float* __restrict__ out) {
    extern __shared__ char smem[];
    uint32_t sb = smem_u32(smem);
    int tid = threadIdx.x;
    int wid = tid >> 5;
    int lane = tid & 31;

    // Grouped rasterization for L2 reuse
    const int num_pid_n = N_DIM / BN; // 128
    const int GROUP = 8;
    int pid = blockIdx.x;
    int npg = GROUP * num_pid_n;
    int group_id = pid / npg;
    int first_m = group_id * GROUP;
    int pid_m = first_m + ((pid % npg) % GROUP);
    int pid_n = (pid % npg) / GROUP;

    const __nv_bfloat16* Abase = g_xq + (size_t)pid_m * BM * K_DIM;
    const __nv_bfloat16* Bbase = g_wt + (size_t)pid_n * BN * K_DIM;

    int WM = (wid & 1) * 64;   // warp m offset (0 or 64)
    int WN = (wid >> 1) * 32;  // warp n offset (0,32,64,96)

    float acc[4][4][4];
#pragma unroll
    for (int i = 0; i < 4; i++)
#pragma unroll
        for (int j = 0; j < 4; j++)
#pragma unroll
            for (int q = 0; q < 4; q++) acc[i][j][q] = 0.f;

    // ldmatrix base offsets (k-step selects bits 5-6 by XOR)
    uint32_t a_off[4];
#pragma unroll
    for (int i = 0; i < 4; i++) {
        int row = WM + 16 * i + (lane & 15);
        a_off[i] = swz(row, ((lane >> 4) & 1) * 16);
    }
    uint32_t b_off[2];
#pragma unroll
    for (int p = 0; p < 2; p++) {
        int n = WN + 16 * p + (lane & 7) + ((lane >> 4) & 1) * 8;
        b_off[p] = (uint32_t)(BM * ROWB) + swz(n, ((lane >> 3) & 1) * 16);
    }

    // Prologue: fill 2 of 3 stages
    load_chunk(sb + 0 * STAGE_BYTES, Abase, Bbase, 0, tid);
    load_chunk(sb + 1 * STAGE_BYTES, Abase, Bbase, 1, tid);

    int slot = 0, lslot = 2;
#pragma unroll 1
    for (int kc = 0; kc < NKC; kc++) {
        if (kc < NKC - 1) cp_wait1(); else cp_wait0();
        __syncthreads();
        // Refill the slot freed last iteration
        if (kc + 2 < NKC) {
            load_chunk(sb + lslot * STAGE_BYTES, Abase, Bbase, kc + 2, tid);
            lslot++; if (lslot == STAGES) lslot = 0;
        }
        uint32_t stage = sb + slot * STAGE_BYTES;
        slot++; if (slot == STAGES) slot = 0;
#pragma unroll
        for (int ks = 0; ks < 4; ks++) {
            uint32_t kx = (uint32_t)(ks * 32);
            uint32_t ua[4][4], ub[2][4];
#pragma unroll
            for (int i = 0; i < 4; i++) ldm_x4(ua[i], stage + (a_off[i] ^ kx));
#pragma unroll
            for (int p = 0; p < 2; p++) ldm_x4(ub[p], stage + (b_off[p] ^ kx));
#pragma unroll
            for (int p = 0; p < 2; p++)
#pragma unroll
                for (int i = 0; i < 4; i++) {
                    hmma(acc[i][2 * p],     ua[i], ub[p]);
                    hmma(acc[i][2 * p + 1], ua[i], ub[p] + 2);
                }
        }
    }

    // Epilogue: scale by s[m]*wscale and store
    float ws = g_wscale;
#pragma unroll
    for (int i = 0; i < 4; i++) {
        int row0 = pid_m * BM + WM + 16 * i + (lane >> 2);
        float s0 = g_sx[row0] * ws;
        float s1 = g_sx[row0 + 8] * ws;
        float* r0 = out + (size_t)row0 * N_DIM + pid_n * BN + WN;
        float* r1 = r0 + (size_t)8 * N_DIM;
#pragma unroll
        for (int j = 0; j < 4; j++) {
            int col = 8 * j + 2 * (lane & 3);
            float2 v0 = make_float2(acc[i][j][0] * s0, acc[i][j][1] * s0);
            float2 v1 = make_float2(acc[i][j][2] * s1, acc[i][j][3] * s1);
            *reinterpret_cast<float2*>(r0 + col) = v0;
            *reinterpret_cast<float2*>(r1 + col) = v1;
        }
    }
}

// ============================================================================
// Launch
// ============================================================================
extern "C" void kernel_launch(void* const* d_in, const int* in_sizes, int n_in,
                              void* d_out, int out_size) {
    const float* x = (const float*)d_in[0];
    const float* w = (const float*)d_in[1];
    if (n_in >= 2 && in_sizes[0] == 67108864) { // defensive: identify by size
        w = (const float*)d_in[0];
        x = (const float*)d_in[1];
    }
    float* out = (float*)d_out;

    cudaFuncSetAttribute(k_gemm, cudaFuncAttributeMaxDynamicSharedMemorySize, GEMM_SMEM);

    k_wabs<<<2048, 256>>>(w);        // includes deterministic final reduce
    k_wquant<<<16384, 256>>>(w);
    k_xquant<<<M_DIM, 128>>>(x);
    k_gemm<<<(M_DIM / BM) * (N_DIM / BN), GTHREADS, GEMM_SMEM>>>(out);
}